// round 14
// baseline (speedup 1.0000x reference)
#include <cuda_runtime.h>
#include <cuda_fp16.h>
#include <math.h>
#include <stdint.h>

// ============================================================================
// Fused GPTQ int4 GEMM for sm_103 via mma.sync (HMMA):
//   1) prepass  : X fp32->fp16 AND QW int4+SC -> fp16 WH[N][K] (one kernel)
//   2) gemm_f16 : Y = XH @ WH^T. CTA 128x128, 8 warps of 64x32, BK=64,
//                 3-stage cp.async ring, XOR-swizzled smem, 2 CTAs/SM,
//                 B-fragment register double-buffering across k-steps.
// ============================================================================

#define BM 128
#define BN 128
#define BK 64
#define NSTAGE 3
#define NT 256
#define A_BYTES (BM * BK * 2)               // 16384
#define STAGE_BYTES (2 * BM * BK * 2)       // 32768
#define SMEM_BYTES (NSTAGE * STAGE_BYTES)   // 98304

#define MAX_XH (8192L * 4096L)
#define MAX_WH (4096L * 11008L)
__device__ __half g_XH[MAX_XH];
__device__ __half g_WH[MAX_WH];

// ---------------- PTX helpers ----------------
__device__ __forceinline__ uint32_t smem_u32(const void* p) {
    uint32_t a;
    asm("{ .reg .u64 t; cvta.to.shared.u64 t, %1; cvt.u32.u64 %0, t; }"
        : "=r"(a) : "l"(p));
    return a;
}
#define CP_ASYNC16(dst, src) \
    asm volatile("cp.async.cg.shared.global [%0], [%1], 16;" \
                 :: "r"(dst), "l"(src) : "memory")
#define CP_COMMIT() asm volatile("cp.async.commit_group;" ::: "memory")
#define CP_WAIT1()  asm volatile("cp.async.wait_group 1;" ::: "memory")

#define LDSM_X4(r0, r1, r2, r3, addr) \
    asm volatile("ldmatrix.sync.aligned.m8n8.x4.shared.b16 {%0,%1,%2,%3}, [%4];" \
                 : "=r"(r0), "=r"(r1), "=r"(r2), "=r"(r3) : "r"(addr))

__device__ __forceinline__ void mma16816(float* d, const uint32_t* a,
                                         const uint32_t* b) {
    asm volatile(
        "mma.sync.aligned.m16n8k16.row.col.f32.f16.f16.f32 "
        "{%0,%1,%2,%3}, {%4,%5,%6,%7}, {%8,%9}, {%0,%1,%2,%3};"
        : "+f"(d[0]), "+f"(d[1]), "+f"(d[2]), "+f"(d[3])
        : "r"(a[0]), "r"(a[1]), "r"(a[2]), "r"(a[3]), "r"(b[0]), "r"(b[1]));
}

// ============================================================================
// Fused prepass: blocks [0, cvtBlocks) convert X; the rest dequantize W.
// ============================================================================
__global__ void prepass(const float* __restrict__ X, const int* __restrict__ QW,
                        const float* __restrict__ SC,
                        __half* __restrict__ XH, __half* __restrict__ WH,
                        long totX, int N, int K, int G, long cvtBlocks) {
    if (blockIdx.x < cvtBlocks) {
        long i = (blockIdx.x * (long)blockDim.x + threadIdx.x) * 8;
        if (i >= totX) return;
        if (i + 8 <= totX) {
            float4 f0 = *reinterpret_cast<const float4*>(X + i);
            float4 f1 = *reinterpret_cast<const float4*>(X + i + 4);
            __half2 h0 = __floats2half2_rn(f0.x, f0.y);
            __half2 h1 = __floats2half2_rn(f0.z, f0.w);
            __half2 h2 = __floats2half2_rn(f1.x, f1.y);
            __half2 h3 = __floats2half2_rn(f1.z, f1.w);
            uint4 o;
            o.x = *reinterpret_cast<uint32_t*>(&h0);
            o.y = *reinterpret_cast<uint32_t*>(&h1);
            o.z = *reinterpret_cast<uint32_t*>(&h2);
            o.w = *reinterpret_cast<uint32_t*>(&h3);
            *reinterpret_cast<uint4*>(XH + i) = o;
        } else {
            for (long j = i; j < totX; j++) XH[j] = __float2half_rn(X[j]);
        }
    } else {
        const int kper = K >> 3;
        long id = (blockIdx.x - cvtBlocks) * (long)blockDim.x + threadIdx.x;
        long n = id / kper;
        int kq = (int)(id - n * kper);
        if (n >= N) return;
        unsigned q = (unsigned)__ldg(QW + (size_t)kq * N + n);
        float sc = __ldg(SC + (size_t)((kq * 8) / G) * N + n);
        uint4 o;
        uint32_t* op = &o.x;
        #pragma unroll
        for (int j = 0; j < 4; j++) {
            float f0 = (float)((int)((q >> (8 * j)) & 15u) - 8) * sc;
            float f1 = (float)((int)((q >> (8 * j + 4)) & 15u) - 8) * sc;
            __half2 h = __floats2half2_rn(f0, f1);
            op[j] = *reinterpret_cast<uint32_t*>(&h);
        }
        *reinterpret_cast<uint4*>(WH + (size_t)n * K + (size_t)kq * 8) = o;
    }
}

// ============================================================================
// Main GEMM: Y[M][N] = XH[M][K] @ WH[N][K]^T  (fp16 x fp16 -> fp32 acc)
// CTA 128x128, 8 warps (2x4) of 64x32, BK=64, 3-stage cp.async, 2 CTAs/SM.
// ============================================================================
__global__ __launch_bounds__(NT, 2)
void gemm_f16(const __half* __restrict__ A, const __half* __restrict__ B,
              float* __restrict__ Y, int M, int N, int K) {
    extern __shared__ char smem[];
    const uint32_t sbase = smem_u32(smem);
    const int tid = threadIdx.x;
    const int lane = tid & 31;
    const int wid = tid >> 5;
    const int wm = wid >> 2;   // 0..1 -> 64-row band
    const int wn = wid & 3;    // 0..3 -> 32-col band

    // GROUP_M=8 rasterization: 8 CTA-rows share each B tile via L2
    const int num_m = M / BM, num_n = N / BN;
    const int per_group = 8 * num_n;
    const int gid = blockIdx.x / per_group;
    const int first_m = gid * 8;
    const int gsz = min(8, num_m - first_m);
    const int rem = blockIdx.x % per_group;
    const int pid_m = first_m + rem % gsz;
    const int pid_n = rem / gsz;
    const int bm0 = pid_m * BM;
    const int bn0 = pid_n * BN;

    const int nK = K / BK;
    const __half* Ag = A + (size_t)bm0 * K;
    const __half* Bg = B + (size_t)bn0 * K;

    // cp.async: 1024 16B chunks per tile, 4 per thread per operand.
    // physical chunk col = col ^ (row & 7)  (conflict-free vs ldmatrix)
    auto fetch = [&](int kt) {
        const int st = kt % NSTAGE;
        const uint32_t sA = sbase + st * STAGE_BYTES;
        const uint32_t sB = sA + A_BYTES;
        const __half* ga = Ag + kt * BK;
        const __half* gb = Bg + kt * BK;
        #pragma unroll
        for (int i = 0; i < 4; i++) {
            int id = tid + i * NT;
            int row = id >> 3, col = id & 7;
            uint32_t d = sA + row * 128 + ((col ^ (row & 7)) << 4);
            CP_ASYNC16(d, ga + (size_t)row * K + col * 8);
        }
        #pragma unroll
        for (int i = 0; i < 4; i++) {
            int id = tid + i * NT;
            int row = id >> 3, col = id & 7;
            uint32_t d = sB + row * 128 + ((col ^ (row & 7)) << 4);
            CP_ASYNC16(d, gb + (size_t)row * K + col * 8);
        }
    };

    // ldmatrix lane addressing
    const int rowA = wm * 64 + (lane & 15);
    const int rowB = wn * 32 + (lane & 15);
    uint32_t swA[4], swB[4];
    #pragma unroll
    for (int ks = 0; ks < 4; ks++) {
        uint32_t c = 2 * ks + (lane >> 4);
        swA[ks] = (c ^ (rowA & 7)) << 4;
        swB[ks] = (c ^ (rowB & 7)) << 4;
    }

    float acc[4][4][4];
    #pragma unroll
    for (int i = 0; i < 4; i++)
        #pragma unroll
        for (int j = 0; j < 4; j++)
            #pragma unroll
            for (int v = 0; v < 4; v++) acc[i][j][v] = 0.f;

    // B fragments double-buffered across ks (bf[buf][nf][2])
    auto loadB = [&](uint32_t sB, int ks, uint32_t bf[4][2]) {
        uint32_t p0, p1, p2, p3, r0, r1, r2, r3;
        LDSM_X4(p0, p1, p2, p3, sB + swB[ks]);
        LDSM_X4(r0, r1, r2, r3, sB + 16 * 128 + swB[ks]);
        bf[0][0] = p0; bf[0][1] = p2;
        bf[1][0] = p1; bf[1][1] = p3;
        bf[2][0] = r0; bf[2][1] = r2;
        bf[3][0] = r1; bf[3][1] = r3;
    };

    auto compute = [&](int st) {
        const uint32_t sA = sbase + st * STAGE_BYTES + rowA * 128;
        const uint32_t sB = sbase + st * STAGE_BYTES + A_BYTES + rowB * 128;
        uint32_t bf[2][4][2];
        loadB(sB, 0, bf[0]);
        #pragma unroll
        for (int ks = 0; ks < 4; ks++) {
            uint32_t a[4][4];
            #pragma unroll
            for (int mf = 0; mf < 4; mf++)
                LDSM_X4(a[mf][0], a[mf][1], a[mf][2], a[mf][3],
                        sA + mf * 16 * 128 + swA[ks]);
            if (ks < 3) loadB(sB, ks + 1, bf[(ks + 1) & 1]);  // prefetch next B
            #pragma unroll
            for (int mf = 0; mf < 4; mf++)
                #pragma unroll
                for (int nf = 0; nf < 4; nf++)
                    mma16816(acc[mf][nf], a[mf], bf[ks & 1][nf]);
        }
    };

    // ---- 3-stage pipeline (2 in flight) ----
    fetch(0); CP_COMMIT();
    fetch(1); CP_COMMIT();
    for (int kt = 0; kt < nK; kt++) {
        CP_WAIT1();
        __syncthreads();
        if (kt + 2 < nK) { fetch(kt + 2); CP_COMMIT(); }
        else { CP_COMMIT(); }  // keep group count aligned with waits
        compute(kt % NSTAGE);
    }

    // ---- epilogue ----
    const int g = lane >> 2;
    const int t2 = (lane & 3) * 2;
    #pragma unroll
    for (int mf = 0; mf < 4; mf++) {
        #pragma unroll
        for (int nf = 0; nf < 4; nf++) {
            int row = bm0 + wm * 64 + mf * 16 + g;
            int col = bn0 + wn * 32 + nf * 8 + t2;
            float* y0 = Y + (size_t)row * N + col;
            float* y1 = y0 + (size_t)8 * N;
            *reinterpret_cast<float2*>(y0) = make_float2(acc[mf][nf][0], acc[mf][nf][1]);
            *reinterpret_cast<float2*>(y1) = make_float2(acc[mf][nf][2], acc[mf][nf][3]);
        }
    }
}

// ============================================================================
// Fallback SIMT fp32 kernel (known-correct) for non-tiling shapes
// ============================================================================
#define FBM 128
#define FBN 128
#define FBK 32
__global__ __launch_bounds__(256, 2)
void int4gemm_fallback(const float* __restrict__ X, const int* __restrict__ QW,
                       const float* __restrict__ SC, float* __restrict__ Y,
                       int M, int N, int K, int G)
{
    __shared__ float Xs[FBK][FBM + 4];
    __shared__ float Ws[FBK][FBN];
    const int tid = threadIdx.x;
    const int bn0 = blockIdx.x * FBN, bm0 = blockIdx.y * FBM;
    const int xm = tid >> 3, xk = (tid & 7) * 4;
    const int wn = tid & 127, wr = tid >> 7;
    const int tx = tid & 15, ty = tid >> 4;
    const int numKT = (K + FBK - 1) / FBK;
    float acc[8][8];
    #pragma unroll
    for (int i = 0; i < 8; i++)
        #pragma unroll
        for (int j = 0; j < 8; j++) acc[i][j] = 0.f;

    for (int kt = 0; kt < numKT; kt++) {
        const int kbase = kt * FBK;
        #pragma unroll
        for (int i = 0; i < 4; i++) {
            int m = bm0 + xm + i * 32;
            float4 v = make_float4(0.f, 0.f, 0.f, 0.f);
            if (m < M && kbase + xk + 3 < K)
                v = *reinterpret_cast<const float4*>(&X[(size_t)m * K + kbase + xk]);
            Xs[xk + 0][xm + i * 32] = v.x; Xs[xk + 1][xm + i * 32] = v.y;
            Xs[xk + 2][xm + i * 32] = v.z; Xs[xk + 3][xm + i * 32] = v.w;
        }
        #pragma unroll
        for (int i = 0; i < 2; i++) {
            int r = wr + i * 2, n = bn0 + wn;
            unsigned q = 0; float sc = 0.f;
            if (n < N && (kbase + r * 8) < K) {
                q = (unsigned)QW[(size_t)(kt * (FBK / 8) + r) * N + n];
                sc = SC[(size_t)((kbase + r * 8) / G) * N + n];
            }
            #pragma unroll
            for (int j = 0; j < 8; j++)
                Ws[r * 8 + j][wn] = (float)((int)((q >> (4 * j)) & 15u) - 8) * sc;
        }
        __syncthreads();
        #pragma unroll
        for (int kk = 0; kk < FBK; kk++) {
            float xv[8], wv[8];
            #pragma unroll
            for (int i = 0; i < 8; i++) { xv[i] = Xs[kk][ty * 8 + i]; wv[i] = Ws[kk][tx * 8 + i]; }
            #pragma unroll
            for (int i = 0; i < 8; i++)
                #pragma unroll
                for (int j = 0; j < 8; j++) acc[i][j] = fmaf(xv[i], wv[j], acc[i][j]);
        }
        __syncthreads();
    }
    #pragma unroll
    for (int i = 0; i < 8; i++) {
        int m = bm0 + ty * 8 + i;
        if (m >= M) continue;
        #pragma unroll
        for (int j = 0; j < 8; j++) {
            int n = bn0 + tx * 8 + j;
            if (n < N) Y[(size_t)m * N + n] = acc[i][j];
        }
    }
}

// ============================================================================
// Launch — shapes derived from element counts only (graph-capture safe)
// ============================================================================
extern "C" void kernel_launch(void* const* d_in, const int* in_sizes, int n_in,
                              void* d_out, int out_size)
{
    const float* X  = (const float*)d_in[0];
    const int*   QW = (const int*)d_in[1];
    const float* SC = (const float*)d_in[2];
    float*       Y  = (float*)d_out;

    double s0 = (double)in_sizes[0], s1 = (double)in_sizes[1], so = (double)out_size;
    long K = (long)(sqrt(8.0 * s0 * s1 / so) + 0.5);
    long M = (long)in_sizes[0] / K;
    long N = (long)out_size / M;
    long G = (K * N) / (long)in_sizes[2];

    bool tc_ok = (M % BM == 0) && (N % BN == 0) && (K % BK == 0) &&
                 (G % 8 == 0) && (K / BK >= 2) &&
                 (M * K <= MAX_XH) && (K * N <= MAX_WH);

    if (tc_ok) {
        __half* XH = nullptr; __half* WH = nullptr;
        cudaGetSymbolAddress((void**)&XH, g_XH);
        cudaGetSymbolAddress((void**)&WH, g_WH);

        long totX = M * K;
        long cvtBlocks = (totX + 256L * 8 - 1) / (256L * 8);
        long totW = N * (K / 8);
        long dqBlocks = (totW + 255) / 256;
        prepass<<<(unsigned)(cvtBlocks + dqBlocks), 256>>>(
            X, QW, SC, XH, WH, totX, (int)N, (int)K, (int)G, cvtBlocks);

        cudaFuncSetAttribute(gemm_f16,
                             cudaFuncAttributeMaxDynamicSharedMemorySize,
                             SMEM_BYTES);
        unsigned grid = (unsigned)((M / BM) * (N / BN));
        gemm_f16<<<grid, NT, SMEM_BYTES>>>(XH, WH, Y, (int)M, (int)N, (int)K);
    } else {
        dim3 grid((unsigned)((N + FBN - 1) / FBN), (unsigned)((M + FBM - 1) / FBM));
        int4gemm_fallback<<<grid, 256>>>(X, QW, SC, Y, (int)M, (int)N, (int)K, (int)G);
    }
}

// round 15
// speedup vs baseline: 1.0004x; 1.0004x over previous
#include <cuda_runtime.h>
#include <cuda_fp16.h>
#include <math.h>
#include <stdint.h>

// ============================================================================
// Fused GPTQ int4 GEMM for sm_103 via mma.sync (HMMA):
//   1) prepass  : X fp32->fp16 AND QW int4+SC -> fp16 WH[N][K] (one kernel)
//   2) gemm_f16 : Y = XH @ WH^T. CTA 128x128, 8 warps of 64x32, BK=64,
//                 3-stage cp.async ring, XOR-swizzled smem, 2 CTAs/SM,
//                 B-fragment register double-buffering across k-steps.
// ============================================================================

#define BM 128
#define BN 128
#define BK 64
#define NSTAGE 3
#define NT 256
#define A_BYTES (BM * BK * 2)               // 16384
#define STAGE_BYTES (2 * BM * BK * 2)       // 32768
#define SMEM_BYTES (NSTAGE * STAGE_BYTES)   // 98304

#define MAX_XH (8192L * 4096L)
#define MAX_WH (4096L * 11008L)
__device__ __half g_XH[MAX_XH];
__device__ __half g_WH[MAX_WH];

// ---------------- PTX helpers ----------------
__device__ __forceinline__ uint32_t smem_u32(const void* p) {
    uint32_t a;
    asm("{ .reg .u64 t; cvta.to.shared.u64 t, %1; cvt.u32.u64 %0, t; }"
        : "=r"(a) : "l"(p));
    return a;
}
#define CP_ASYNC16(dst, src) \
    asm volatile("cp.async.cg.shared.global [%0], [%1], 16;" \
                 :: "r"(dst), "l"(src) : "memory")
#define CP_COMMIT() asm volatile("cp.async.commit_group;" ::: "memory")
#define CP_WAIT1()  asm volatile("cp.async.wait_group 1;" ::: "memory")

#define LDSM_X4(r0, r1, r2, r3, addr) \
    asm volatile("ldmatrix.sync.aligned.m8n8.x4.shared.b16 {%0,%1,%2,%3}, [%4];" \
                 : "=r"(r0), "=r"(r1), "=r"(r2), "=r"(r3) : "r"(addr))

__device__ __forceinline__ void mma16816(float* d, const uint32_t* a,
                                         const uint32_t* b) {
    asm volatile(
        "mma.sync.aligned.m16n8k16.row.col.f32.f16.f16.f32 "
        "{%0,%1,%2,%3}, {%4,%5,%6,%7}, {%8,%9}, {%0,%1,%2,%3};"
        : "+f"(d[0]), "+f"(d[1]), "+f"(d[2]), "+f"(d[3])
        : "r"(a[0]), "r"(a[1]), "r"(a[2]), "r"(a[3]), "r"(b[0]), "r"(b[1]));
}

// ============================================================================
// Fused prepass: blocks [0, cvtBlocks) convert X; the rest dequantize W.
// ============================================================================
__global__ void prepass(const float* __restrict__ X, const int* __restrict__ QW,
                        const float* __restrict__ SC,
                        __half* __restrict__ XH, __half* __restrict__ WH,
                        long totX, int N, int K, int G, long cvtBlocks) {
    if (blockIdx.x < cvtBlocks) {
        long i = (blockIdx.x * (long)blockDim.x + threadIdx.x) * 8;
        if (i >= totX) return;
        if (i + 8 <= totX) {
            float4 f0 = *reinterpret_cast<const float4*>(X + i);
            float4 f1 = *reinterpret_cast<const float4*>(X + i + 4);
            __half2 h0 = __floats2half2_rn(f0.x, f0.y);
            __half2 h1 = __floats2half2_rn(f0.z, f0.w);
            __half2 h2 = __floats2half2_rn(f1.x, f1.y);
            __half2 h3 = __floats2half2_rn(f1.z, f1.w);
            uint4 o;
            o.x = *reinterpret_cast<uint32_t*>(&h0);
            o.y = *reinterpret_cast<uint32_t*>(&h1);
            o.z = *reinterpret_cast<uint32_t*>(&h2);
            o.w = *reinterpret_cast<uint32_t*>(&h3);
            *reinterpret_cast<uint4*>(XH + i) = o;
        } else {
            for (long j = i; j < totX; j++) XH[j] = __float2half_rn(X[j]);
        }
    } else {
        const int kper = K >> 3;
        long id = (blockIdx.x - cvtBlocks) * (long)blockDim.x + threadIdx.x;
        long n = id / kper;
        int kq = (int)(id - n * kper);
        if (n >= N) return;
        unsigned q = (unsigned)__ldg(QW + (size_t)kq * N + n);
        float sc = __ldg(SC + (size_t)((kq * 8) / G) * N + n);
        uint4 o;
        uint32_t* op = &o.x;
        #pragma unroll
        for (int j = 0; j < 4; j++) {
            float f0 = (float)((int)((q >> (8 * j)) & 15u) - 8) * sc;
            float f1 = (float)((int)((q >> (8 * j + 4)) & 15u) - 8) * sc;
            __half2 h = __floats2half2_rn(f0, f1);
            op[j] = *reinterpret_cast<uint32_t*>(&h);
        }
        *reinterpret_cast<uint4*>(WH + (size_t)n * K + (size_t)kq * 8) = o;
    }
}

// ============================================================================
// Main GEMM: Y[M][N] = XH[M][K] @ WH[N][K]^T  (fp16 x fp16 -> fp32 acc)
// CTA 128x128, 8 warps (2x4) of 64x32, BK=64, 3-stage cp.async, 2 CTAs/SM.
// ============================================================================
__global__ __launch_bounds__(NT, 2)
void gemm_f16(const __half* __restrict__ A, const __half* __restrict__ B,
              float* __restrict__ Y, int M, int N, int K) {
    extern __shared__ char smem[];
    const uint32_t sbase = smem_u32(smem);
    const int tid = threadIdx.x;
    const int lane = tid & 31;
    const int wid = tid >> 5;
    const int wm = wid >> 2;   // 0..1 -> 64-row band
    const int wn = wid & 3;    // 0..3 -> 32-col band

    // GROUP_M=8 rasterization: 8 CTA-rows share each B tile via L2
    const int num_m = M / BM, num_n = N / BN;
    const int per_group = 8 * num_n;
    const int gid = blockIdx.x / per_group;
    const int first_m = gid * 8;
    const int gsz = min(8, num_m - first_m);
    const int rem = blockIdx.x % per_group;
    const int pid_m = first_m + rem % gsz;
    const int pid_n = rem / gsz;
    const int bm0 = pid_m * BM;
    const int bn0 = pid_n * BN;

    const int nK = K / BK;
    const __half* Ag = A + (size_t)bm0 * K;
    const __half* Bg = B + (size_t)bn0 * K;

    // cp.async: 1024 16B chunks per tile, 4 per thread per operand.
    // physical chunk col = col ^ (row & 7)  (conflict-free vs ldmatrix)
    auto fetch = [&](int kt) {
        const int st = kt % NSTAGE;
        const uint32_t sA = sbase + st * STAGE_BYTES;
        const uint32_t sB = sA + A_BYTES;
        const __half* ga = Ag + kt * BK;
        const __half* gb = Bg + kt * BK;
        #pragma unroll
        for (int i = 0; i < 4; i++) {
            int id = tid + i * NT;
            int row = id >> 3, col = id & 7;
            uint32_t d = sA + row * 128 + ((col ^ (row & 7)) << 4);
            CP_ASYNC16(d, ga + (size_t)row * K + col * 8);
        }
        #pragma unroll
        for (int i = 0; i < 4; i++) {
            int id = tid + i * NT;
            int row = id >> 3, col = id & 7;
            uint32_t d = sB + row * 128 + ((col ^ (row & 7)) << 4);
            CP_ASYNC16(d, gb + (size_t)row * K + col * 8);
        }
    };

    // ldmatrix lane addressing
    const int rowA = wm * 64 + (lane & 15);
    const int rowB = wn * 32 + (lane & 15);
    uint32_t swA[4], swB[4];
    #pragma unroll
    for (int ks = 0; ks < 4; ks++) {
        uint32_t c = 2 * ks + (lane >> 4);
        swA[ks] = (c ^ (rowA & 7)) << 4;
        swB[ks] = (c ^ (rowB & 7)) << 4;
    }

    float acc[4][4][4];
    #pragma unroll
    for (int i = 0; i < 4; i++)
        #pragma unroll
        for (int j = 0; j < 4; j++)
            #pragma unroll
            for (int v = 0; v < 4; v++) acc[i][j][v] = 0.f;

    // B fragments double-buffered across ks (bf[buf][nf][2])
    auto loadB = [&](uint32_t sB, int ks, uint32_t bf[4][2]) {
        uint32_t p0, p1, p2, p3, r0, r1, r2, r3;
        LDSM_X4(p0, p1, p2, p3, sB + swB[ks]);
        LDSM_X4(r0, r1, r2, r3, sB + 16 * 128 + swB[ks]);
        bf[0][0] = p0; bf[0][1] = p2;
        bf[1][0] = p1; bf[1][1] = p3;
        bf[2][0] = r0; bf[2][1] = r2;
        bf[3][0] = r1; bf[3][1] = r3;
    };

    auto compute = [&](int st) {
        const uint32_t sA = sbase + st * STAGE_BYTES + rowA * 128;
        const uint32_t sB = sbase + st * STAGE_BYTES + A_BYTES + rowB * 128;
        uint32_t bf[2][4][2];
        loadB(sB, 0, bf[0]);
        #pragma unroll
        for (int ks = 0; ks < 4; ks++) {
            uint32_t a[4][4];
            #pragma unroll
            for (int mf = 0; mf < 4; mf++)
                LDSM_X4(a[mf][0], a[mf][1], a[mf][2], a[mf][3],
                        sA + mf * 16 * 128 + swA[ks]);
            if (ks < 3) loadB(sB, ks + 1, bf[(ks + 1) & 1]);  // prefetch next B
            #pragma unroll
            for (int mf = 0; mf < 4; mf++)
                #pragma unroll
                for (int nf = 0; nf < 4; nf++)
                    mma16816(acc[mf][nf], a[mf], bf[ks & 1][nf]);
        }
    };

    // ---- 3-stage pipeline (2 in flight) ----
    fetch(0); CP_COMMIT();
    fetch(1); CP_COMMIT();
    for (int kt = 0; kt < nK; kt++) {
        CP_WAIT1();
        __syncthreads();
        if (kt + 2 < nK) { fetch(kt + 2); CP_COMMIT(); }
        else { CP_COMMIT(); }  // keep group count aligned with waits
        compute(kt % NSTAGE);
    }

    // ---- epilogue ----
    const int g = lane >> 2;
    const int t2 = (lane & 3) * 2;
    #pragma unroll
    for (int mf = 0; mf < 4; mf++) {
        #pragma unroll
        for (int nf = 0; nf < 4; nf++) {
            int row = bm0 + wm * 64 + mf * 16 + g;
            int col = bn0 + wn * 32 + nf * 8 + t2;
            float* y0 = Y + (size_t)row * N + col;
            float* y1 = y0 + (size_t)8 * N;
            *reinterpret_cast<float2*>(y0) = make_float2(acc[mf][nf][0], acc[mf][nf][1]);
            *reinterpret_cast<float2*>(y1) = make_float2(acc[mf][nf][2], acc[mf][nf][3]);
        }
    }
}

// ============================================================================
// Fallback SIMT fp32 kernel (known-correct) for non-tiling shapes
// ============================================================================
#define FBM 128
#define FBN 128
#define FBK 32
__global__ __launch_bounds__(256, 2)
void int4gemm_fallback(const float* __restrict__ X, const int* __restrict__ QW,
                       const float* __restrict__ SC, float* __restrict__ Y,
                       int M, int N, int K, int G)
{
    __shared__ float Xs[FBK][FBM + 4];
    __shared__ float Ws[FBK][FBN];
    const int tid = threadIdx.x;
    const int bn0 = blockIdx.x * FBN, bm0 = blockIdx.y * FBM;
    const int xm = tid >> 3, xk = (tid & 7) * 4;
    const int wn = tid & 127, wr = tid >> 7;
    const int tx = tid & 15, ty = tid >> 4;
    const int numKT = (K + FBK - 1) / FBK;
    float acc[8][8];
    #pragma unroll
    for (int i = 0; i < 8; i++)
        #pragma unroll
        for (int j = 0; j < 8; j++) acc[i][j] = 0.f;

    for (int kt = 0; kt < numKT; kt++) {
        const int kbase = kt * FBK;
        #pragma unroll
        for (int i = 0; i < 4; i++) {
            int m = bm0 + xm + i * 32;
            float4 v = make_float4(0.f, 0.f, 0.f, 0.f);
            if (m < M && kbase + xk + 3 < K)
                v = *reinterpret_cast<const float4*>(&X[(size_t)m * K + kbase + xk]);
            Xs[xk + 0][xm + i * 32] = v.x; Xs[xk + 1][xm + i * 32] = v.y;
            Xs[xk + 2][xm + i * 32] = v.z; Xs[xk + 3][xm + i * 32] = v.w;
        }
        #pragma unroll
        for (int i = 0; i < 2; i++) {
            int r = wr + i * 2, n = bn0 + wn;
            unsigned q = 0; float sc = 0.f;
            if (n < N && (kbase + r * 8) < K) {
                q = (unsigned)QW[(size_t)(kt * (FBK / 8) + r) * N + n];
                sc = SC[(size_t)((kbase + r * 8) / G) * N + n];
            }
            #pragma unroll
            for (int j = 0; j < 8; j++)
                Ws[r * 8 + j][wn] = (float)((int)((q >> (4 * j)) & 15u) - 8) * sc;
        }
        __syncthreads();
        #pragma unroll
        for (int kk = 0; kk < FBK; kk++) {
            float xv[8], wv[8];
            #pragma unroll
            for (int i = 0; i < 8; i++) { xv[i] = Xs[kk][ty * 8 + i]; wv[i] = Ws[kk][tx * 8 + i]; }
            #pragma unroll
            for (int i = 0; i < 8; i++)
                #pragma unroll
                for (int j = 0; j < 8; j++) acc[i][j] = fmaf(xv[i], wv[j], acc[i][j]);
        }
        __syncthreads();
    }
    #pragma unroll
    for (int i = 0; i < 8; i++) {
        int m = bm0 + ty * 8 + i;
        if (m >= M) continue;
        #pragma unroll
        for (int j = 0; j < 8; j++) {
            int n = bn0 + tx * 8 + j;
            if (n < N) Y[(size_t)m * N + n] = acc[i][j];
        }
    }
}

// ============================================================================
// Launch — shapes derived from element counts only (graph-capture safe)
// ============================================================================
extern "C" void kernel_launch(void* const* d_in, const int* in_sizes, int n_in,
                              void* d_out, int out_size)
{
    const float* X  = (const float*)d_in[0];
    const int*   QW = (const int*)d_in[1];
    const float* SC = (const float*)d_in[2];
    float*       Y  = (float*)d_out;

    double s0 = (double)in_sizes[0], s1 = (double)in_sizes[1], so = (double)out_size;
    long K = (long)(sqrt(8.0 * s0 * s1 / so) + 0.5);
    long M = (long)in_sizes[0] / K;
    long N = (long)out_size / M;
    long G = (K * N) / (long)in_sizes[2];

    bool tc_ok = (M % BM == 0) && (N % BN == 0) && (K % BK == 0) &&
                 (G % 8 == 0) && (K / BK >= 2) &&
                 (M * K <= MAX_XH) && (K * N <= MAX_WH);

    if (tc_ok) {
        __half* XH = nullptr; __half* WH = nullptr;
        cudaGetSymbolAddress((void**)&XH, g_XH);
        cudaGetSymbolAddress((void**)&WH, g_WH);

        long totX = M * K;
        long cvtBlocks = (totX + 256L * 8 - 1) / (256L * 8);
        long totW = N * (K / 8);
        long dqBlocks = (totW + 255) / 256;
        prepass<<<(unsigned)(cvtBlocks + dqBlocks), 256>>>(
            X, QW, SC, XH, WH, totX, (int)N, (int)K, (int)G, cvtBlocks);

        cudaFuncSetAttribute(gemm_f16,
                             cudaFuncAttributeMaxDynamicSharedMemorySize,
                             SMEM_BYTES);
        unsigned grid = (unsigned)((M / BM) * (N / BN));
        gemm_f16<<<grid, NT, SMEM_BYTES>>>(XH, WH, Y, (int)M, (int)N, (int)K);
    } else {
        dim3 grid((unsigned)((N + FBN - 1) / FBN), (unsigned)((M + FBM - 1) / FBM));
        int4gemm_fallback<<<grid, 256>>>(X, QW, SC, Y, (int)M, (int)N, (int)K, (int)G);
    }
}